// round 4
// baseline (speedup 1.0000x reference)
#include <cuda_runtime.h>
#include <cuda_bf16.h>

// PositionEncoding: out[b,s,:] = is_class ? E_class[class_id] : sincos(v * 2^i * pi)
// B=64, S=8192, 32 levels (E=64), CLASS_NUM=4096.
//
// R3 insight: kernel was MUFU-throughput-bound (4 sincos MUFU ops per thread,
// rt=8/SMSP -> ~57K cyc/SM). Fix: one __sincosf per 4 levels; derive levels
// i+1..i+3 by double-angle (s'=2sc, c'=1-2s^2), 3 FMAs each. MUFU work /4.
//
// Angle reduction (FP64-free, "turns"): reference angle for level i is exactly
// 2^i * a0 with a0 = fl32(v*pi_f) (pow2 scaling commutes with fp32 rounding).
// u = frac(a0 * (1/2pi) * 2^i) via two-float 1/2pi (~47 bits); pow2 scaling and
// frac are exact in fp32. Worst angle err ~2.4e-5 rad, x8 after 3 doublings:
// still << 1e-3 tolerance.

#define NTOK   (64 * 8192)     // 524288 tokens
#define UNROLL 4               // tokens per thread

__global__ __launch_bounds__(256)
void pos_enc_kernel(const float4* __restrict__ values4,    // [NTOK/4]
                    const float4* __restrict__ E_class,    // [4096][16] float4
                    const int4*  __restrict__ class_ids4,  // [NTOK/4]
                    const int4*  __restrict__ is_class4,   // [NTOK/4]
                    float4* __restrict__ out)               // [NTOK][16] float4
{
    unsigned gid  = blockIdx.x * blockDim.x + threadIdx.x;
    unsigned u    = gid & 7u;           // owns levels 4u..4u+3 -> slots 2u, 2u+1
    unsigned grp  = gid >> 3;           // token group (4 tokens)
    unsigned tok0 = grp * UNROLL;
    if (tok0 >= NTOK) return;

    // two-float 1/(2pi): C_HI + C_LO ~ 47 bits (folded at compile time)
    constexpr double INV2PI_D = 0.15915494309189533577;
    constexpr float  C_HI = (float)INV2PI_D;
    constexpr float  C_LO = (float)(INV2PI_D - (double)C_HI);
    const float PI_F     = 3.14159265358979323846f;   // rounds to pi_f32
    const float TWO_PI_F = 6.28318530717958647693f;

    // 2^(4u) as exact fp32 via exponent bits
    float scale_e = __uint_as_float((127u + 4u * u) << 23);

    // ---- 3 vector loads cover all 12 per-token scalars ----
    float4 v4 = __ldg(&values4[grp]);
    int4   c4 = __ldg(&class_ids4[grp]);
    int4   m4 = __ldg(&is_class4[grp]);

    float v[UNROLL]  = { v4.x, v4.y, v4.z, v4.w };
    int   cid[UNROLL]= { c4.x, c4.y, c4.z, c4.w };
    int   ic[UNROLL] = { m4.x, m4.y, m4.z, m4.w };

    // ---- issue all predicated E_class gathers early (overlap latency) ----
    float4 clsA[UNROLL], clsB[UNROLL];
#pragma unroll
    for (int j = 0; j < UNROLL; j++) {
        if (ic[j] == 1) {
            const float4* row = &E_class[(unsigned)cid[j] * 16u + 2u * u];
            clsA[j] = __ldg(row);
            clsB[j] = __ldg(row + 1);
        }
    }

    // ---- compute + streaming store ----
#pragma unroll
    for (int j = 0; j < UNROLL; j++) {
        float4 oa, ob;
        if (ic[j] == 1) {
            oa = clsA[j];
            ob = clsB[j];
        } else {
            float a0   = v[j] * PI_F;                 // fl32(v*pi) — matches reference
            float s_hi = a0 * C_HI;
            float perr = fmaf(a0, C_HI, -s_hi);       // exact residual of a0*C_HI
            float s_lo = fmaf(a0, C_LO, perr);        // two-float tail, ~47 bits total
            float y_hi = s_hi * scale_e;              // exact (pow2 scale)
            float y_lo = s_lo * scale_e;              // exact
            float f    = (y_hi - floorf(y_hi)) + (y_lo - floorf(y_lo)); // exact fracs
            float w0   = f - rintf(f);                // turn in [-0.5, 0.5]

            float s0, c0;
            __sincosf(w0 * TWO_PI_F, &s0, &c0);       // level 4u
            float s1 = 2.0f * s0 * c0;                // level 4u+1 (double angle)
            float c1 = fmaf(-2.0f * s0, s0, 1.0f);
            float s2 = 2.0f * s1 * c1;                // level 4u+2
            float c2 = fmaf(-2.0f * s1, s1, 1.0f);
            float s3 = 2.0f * s2 * c2;                // level 4u+3
            float c3 = fmaf(-2.0f * s2, s2, 1.0f);

            oa = make_float4(s0, c0, s1, c1);
            ob = make_float4(s2, c2, s3, c3);
        }
        float4* dst = &out[(tok0 + j) * 16u + 2u * u];
        __stcs(dst,     oa);                          // evict-first: never re-read
        __stcs(dst + 1, ob);
    }
}

extern "C" void kernel_launch(void* const* d_in, const int* in_sizes, int n_in,
                              void* d_out, int out_size)
{
    const float4* values4    = (const float4*)d_in[0];
    const float4* E_class    = (const float4*)d_in[1];
    const int4*   class_ids4 = (const int4*)d_in[2];
    const int4*   is_class4  = (const int4*)d_in[3];
    float4*       out        = (float4*)d_out;

    const int threads = 256;
    const long long total = (long long)(NTOK / UNROLL) * 8;   // 1,048,576 threads
    const int blocks  = (int)((total + threads - 1) / threads);
    pos_enc_kernel<<<blocks, threads>>>(values4, E_class, class_ids4, is_class4, out);
}

// round 5
// speedup vs baseline: 1.5181x; 1.5181x over previous
#include <cuda_runtime.h>
#include <cuda_bf16.h>

// PositionEncoding: out[b,s,:] = is_class ? E_class[class_id] : sincos(v * 2^i * pi)
// B=64, S=8192, 32 levels (E=64), CLASS_NUM=4096.
//
// R4 = R2's proven memory layout (16 threads/token, one contiguous float4 per
// thread -> perfect 512B warp stores; 3 vectorized scalar LDG.128 per 4 tokens)
// + single __sincosf per slot: even level via reduced-argument sincos, odd
// level via double-angle FMAs (s'=2sc, c'=1-2s^2). R3 taught us the store
// pattern is sacred; MUFU count is secondary.
//
// Angle reduction (FP64-free, "turns"): reference angle for level i is exactly
// 2^i * a0 with a0 = fl32(v*pi_f). u = frac(a0 * (1/2pi) * 2^i) via two-float
// 1/2pi (~47 bits); pow2 scaling and frac are exact in fp32. Angle err
// ~2.4e-5 rad, x2 after one doubling: << 1e-3 tolerance.

#define NTOK   (64 * 8192)     // 524288 tokens
#define UNROLL 4               // tokens per thread

__global__ __launch_bounds__(256)
void pos_enc_kernel(const float4* __restrict__ values4,    // [NTOK/4]
                    const float4* __restrict__ E_class,    // [4096][16] float4
                    const int4*  __restrict__ class_ids4,  // [NTOK/4]
                    const int4*  __restrict__ is_class4,   // [NTOK/4]
                    float4* __restrict__ out)               // [NTOK][16] float4
{
    unsigned gid  = blockIdx.x * blockDim.x + threadIdx.x;
    unsigned t    = gid & 15u;          // float4 slot -> levels 2t, 2t+1
    unsigned grp  = gid >> 4;           // token group (4 tokens)
    unsigned tok0 = grp * UNROLL;
    if (tok0 >= NTOK) return;

    // two-float 1/(2pi): C_HI + C_LO ~ 47 bits (folded at compile time)
    constexpr double INV2PI_D = 0.15915494309189533577;
    constexpr float  C_HI = (float)INV2PI_D;
    constexpr float  C_LO = (float)(INV2PI_D - (double)C_HI);
    const float PI_F     = 3.14159265358979323846f;   // rounds to pi_f32
    const float TWO_PI_F = 6.28318530717958647693f;

    // 2^(2t) as exact fp32 via exponent bits
    float scale_e = __uint_as_float((127u + 2u * t) << 23);

    // ---- 3 vector loads cover all 12 per-token scalars ----
    float4 v4 = __ldg(&values4[grp]);
    int4   c4 = __ldg(&class_ids4[grp]);
    int4   m4 = __ldg(&is_class4[grp]);

    float v[UNROLL]  = { v4.x, v4.y, v4.z, v4.w };
    int   cid[UNROLL]= { c4.x, c4.y, c4.z, c4.w };
    int   ic[UNROLL] = { m4.x, m4.y, m4.z, m4.w };

    // ---- issue all predicated E_class gathers early (overlap latency) ----
    float4 cls[UNROLL];
#pragma unroll
    for (int j = 0; j < UNROLL; j++) {
        if (ic[j] == 1)
            cls[j] = __ldg(&E_class[(unsigned)cid[j] * 16u + t]);
    }

    // ---- compute + streaming store ----
#pragma unroll
    for (int j = 0; j < UNROLL; j++) {
        float4 o;
        if (ic[j] == 1) {
            o = cls[j];
        } else {
            float a0   = v[j] * PI_F;                 // fl32(v*pi) — matches reference
            float s_hi = a0 * C_HI;
            float perr = fmaf(a0, C_HI, -s_hi);       // exact residual of a0*C_HI
            float s_lo = fmaf(a0, C_LO, perr);        // two-float tail, ~47 bits total
            float y_hi = s_hi * scale_e;              // exact (pow2 scale)
            float y_lo = s_lo * scale_e;              // exact
            float f    = (y_hi - floorf(y_hi)) + (y_lo - floorf(y_lo)); // exact fracs
            float w0   = f - rintf(f);                // turn in [-0.5, 0.5]

            float s0, c0;
            __sincosf(w0 * TWO_PI_F, &s0, &c0);       // level 2t
            float s1 = 2.0f * s0 * c0;                // level 2t+1 via double angle
            float c1 = fmaf(-2.0f * s0, s0, 1.0f);
            o = make_float4(s0, c0, s1, c1);
        }
        __stcs(&out[(tok0 + j) * 16u + t], o);        // evict-first: never re-read
    }
}

extern "C" void kernel_launch(void* const* d_in, const int* in_sizes, int n_in,
                              void* d_out, int out_size)
{
    const float4* values4    = (const float4*)d_in[0];
    const float4* E_class    = (const float4*)d_in[1];
    const int4*   class_ids4 = (const int4*)d_in[2];
    const int4*   is_class4  = (const int4*)d_in[3];
    float4*       out        = (float4*)d_out;

    const int threads = 256;
    const long long total = (long long)(NTOK / UNROLL) * 16;   // 2,097,152 threads
    const int blocks  = (int)((total + threads - 1) / threads);
    pos_enc_kernel<<<blocks, threads>>>(values4, E_class, class_ids4, is_class4, out);
}